// round 1
// baseline (speedup 1.0000x reference)
#include <cuda_runtime.h>
#include <cstdint>

// Problem dims (fixed by the dataset)
#define N_SAMPLES 4096
#define D_BASES   64
#define I_IN      512
#define O_OUT     512
#define K_TOTAL   (D_BASES * I_IN)   // 32768

// GEMM tiling
#define BM 128
#define BN 128
#define BK 8
#define NTHREADS 512

// ---------------------------------------------------------------------------
// Packed f32x2 helpers (Blackwell sm_100a+): 2 fp32 FMAs per instruction.
// ---------------------------------------------------------------------------
__device__ __forceinline__ unsigned long long pack2(float x, float y) {
    unsigned long long r;
    asm("mov.b64 %0, {%1, %2};" : "=l"(r) : "f"(x), "f"(y));
    return r;
}
__device__ __forceinline__ void unpack2(unsigned long long v, float& x, float& y) {
    asm("mov.b64 {%0, %1}, %2;" : "=f"(x), "=f"(y) : "l"(v));
}
__device__ __forceinline__ unsigned long long fma2(unsigned long long a,
                                                   unsigned long long b,
                                                   unsigned long long c) {
    unsigned long long d;
    asm("fma.rn.f32x2 %0, %1, %2, %3;" : "=l"(d) : "l"(a), "l"(b), "l"(c));
    return d;
}

// ---------------------------------------------------------------------------
// Fused kernel: out = Z @ W_flat + var @ b
//   Z[n, k]      = var[n, k>>9] * x[n, k&511]   (generated on the fly)
//   W_flat[k, o] = W_1 viewed as [D*I, O] row-major (contiguous as given)
// One CTA computes a 128x128 output tile. 512 threads; each thread owns an
// 8-row x 4-col micro-tile held as 4x4 packed f32x2 accumulators (row pairs).
// ---------------------------------------------------------------------------
__global__ __launch_bounds__(NTHREADS, 1)
void mlp_param_fused_kernel(const float* __restrict__ x,
                            const float* __restrict__ var,
                            const float* __restrict__ W,
                            const float* __restrict__ b1,
                            float* __restrict__ out)
{
    __shared__ float As[BK][BM];     // Z tile, transposed: As[k][m]
    __shared__ float Bs[BK][BN];     // W tile: Bs[k][n]
    __shared__ float Vs[BM][65];     // var tile (padded to kill bank conflicts)

    const int tid = threadIdx.x;
    const int tx  = tid & 31;        // 0..31 -> output col base tx*4
    const int ty  = tid >> 5;        // 0..15 -> output row base ty*8
    const int gr0 = blockIdx.y * BM; // sample-row block
    const int gc0 = blockIdx.x * BN; // output-col block

    // Stage the var tile [128 x 64] into shared once.
    for (int idx = tid; idx < BM * D_BASES; idx += NTHREADS) {
        const int r = idx >> 6;
        const int c = idx & 63;
        Vs[r][c] = var[(gr0 + r) * D_BASES + c];
    }
    __syncthreads();

    // Global-load assignments (coalesced float2 per thread):
    const int ar = tid >> 2;          // 0..127 : A row
    const int ac = (tid & 3) * 2;     // 0,2,4,6: A cols (within BK)
    const int br = tid >> 6;          // 0..7   : B row (within BK)
    const int bc = (tid & 63) * 2;    // 0..126 : B cols

    const float* xrow = x + (gr0 + ar) * I_IN;
    const float* wcol = W + gc0 + bc;

    unsigned long long acc[4][4];     // [row-pair][col] packed f32x2
#pragma unroll
    for (int i = 0; i < 4; ++i)
#pragma unroll
        for (int j = 0; j < 4; ++j) acc[i][j] = 0ULL;

    // Prefetch k-block 0
    float2 aReg, bReg;
    {
        aReg = *reinterpret_cast<const float2*>(xrow + ac);
        const float v = Vs[ar][0];
        aReg.x *= v; aReg.y *= v;
        bReg = *reinterpret_cast<const float2*>(wcol + br * O_OUT);
    }

    const int NKB = K_TOTAL / BK;     // 4096 k-blocks
#pragma unroll 1
    for (int kb = 0; kb < NKB; ++kb) {
        __syncthreads();
        As[ac][ar]     = aReg.x;
        As[ac + 1][ar] = aReg.y;
        *reinterpret_cast<float2*>(&Bs[br][bc]) = bReg;
        __syncthreads();

        // Prefetch next k-block while computing this one.
        if (kb + 1 < NKB) {
            const int knext = (kb + 1) * BK;
            const int d  = knext >> 9;        // basis index (fixed within block)
            const int i0 = knext & (I_IN - 1);
            aReg = *reinterpret_cast<const float2*>(xrow + i0 + ac);
            const float v = Vs[ar][d];
            aReg.x *= v; aReg.y *= v;
            bReg = *reinterpret_cast<const float2*>(wcol + (knext + br) * O_OUT);
        }

#pragma unroll
        for (int kk = 0; kk < BK; ++kk) {
            const float4 bv = *reinterpret_cast<const float4*>(&Bs[kk][tx * 4]);
            unsigned long long b2[4];
            b2[0] = pack2(bv.x, bv.x);
            b2[1] = pack2(bv.y, bv.y);
            b2[2] = pack2(bv.z, bv.z);
            b2[3] = pack2(bv.w, bv.w);
            // Row pairs: two LDS.128 pulls 8 consecutive rows as 4 packed pairs.
            const ulonglong2 av0 = *reinterpret_cast<const ulonglong2*>(&As[kk][ty * 8]);
            const ulonglong2 av1 = *reinterpret_cast<const ulonglong2*>(&As[kk][ty * 8 + 4]);
            const unsigned long long a2[4] = {av0.x, av0.y, av1.x, av1.y};
#pragma unroll
            for (int i = 0; i < 4; ++i)
#pragma unroll
                for (int j = 0; j < 4; ++j)
                    acc[i][j] = fma2(a2[i], b2[j], acc[i][j]);
        }
    }

    // Unpack accumulators into per-row scalars.
    float accf[8][4];
#pragma unroll
    for (int i = 0; i < 4; ++i)
#pragma unroll
        for (int j = 0; j < 4; ++j)
            unpack2(acc[i][j], accf[2 * i][j], accf[2 * i + 1][j]);

    // Bias epilogue: accf[r][j] += sum_d var[row, d] * b1[d, col].
    const int gc = gc0 + tx * 4;
#pragma unroll 1
    for (int d = 0; d < D_BASES; ++d) {
        const float4 bb = *reinterpret_cast<const float4*>(b1 + d * O_OUT + gc);
#pragma unroll
        for (int r = 0; r < 8; ++r) {
            const float v = Vs[ty * 8 + r][d];
            accf[r][0] += v * bb.x;
            accf[r][1] += v * bb.y;
            accf[r][2] += v * bb.z;
            accf[r][3] += v * bb.w;
        }
    }

    // Store 8 rows x float4.
#pragma unroll
    for (int r = 0; r < 8; ++r) {
        float4 o;
        o.x = accf[r][0]; o.y = accf[r][1]; o.z = accf[r][2]; o.w = accf[r][3];
        *reinterpret_cast<float4*>(out + (gr0 + ty * 8 + r) * O_OUT + gc) = o;
    }
}

extern "C" void kernel_launch(void* const* d_in, const int* in_sizes, int n_in,
                              void* d_out, int out_size)
{
    const float* x   = (const float*)d_in[0];  // [4096, 512]
    const float* var = (const float*)d_in[1];  // [4096, 64]
    const float* W   = (const float*)d_in[2];  // [64, 512, 512] == [32768, 512]
    const float* b1  = (const float*)d_in[3];  // [64, 512]
    float* out = (float*)d_out;                // [4096, 512]

    dim3 grid(O_OUT / BN, N_SAMPLES / BM);     // 4 x 32 = 128 CTAs
    mlp_param_fused_kernel<<<grid, NTHREADS>>>(x, var, W, b1, out);
}